// round 9
// baseline (speedup 1.0000x reference)
#include <cuda_runtime.h>
#include <math.h>

// Problem constants
#define NN 64
#define CC 256
#define TT 64
#define VV 25
#define TV 1600          // T*V
#define NTV 102400       // N*T*V (per-channel element count)
#define MTOT 102400      // N*TV  (GEMM M dimension)
#define XSTRIDE_N (CC*TV)

// Scratch (device globals: allocations are forbidden)
__device__ float g_r[(size_t)NN*CC*TV];   // relu(conv) output, layout (n,o,t,v)
__device__ float g_Wt[CC*CC];             // transposed weights: Wt[c*CC + o] = W[o,c]
__device__ float g_sum1[CC], g_sq1[CC];   // BN1 raw stats
// folded BN1 + input-shift coefficients (per input channel c)
__device__ float g_A0[CC], g_A1[CC], g_O0[CC], g_O1[CC];
__device__ int   g_D[CC];
// output-shift coefficients (per output channel o)
__device__ float g_w0o[CC], g_w1o[CC];
__device__ int   g_Do[CC];
// BN2 partial stats (per n, per o) -> deterministic reduction in finalize
__device__ float g_p2s[NN*CC], g_p2q[NN*CC];
__device__ float g_sc2[CC], g_of2[CC];

// ---------------------------------------------------------------------------
// Kernel 1: BN1 stats. One block per channel c; reduce sum & sumsq over n,t,v.
// ---------------------------------------------------------------------------
__global__ void k_stats1(const float* __restrict__ x) {
    int c = blockIdx.x;
    float s = 0.f, ss = 0.f;
    for (int n = 0; n < NN; n++) {
        const float4* p = (const float4*)(x + (size_t)(n * CC + c) * TV);
        for (int i = threadIdx.x; i < TV / 4; i += blockDim.x) {
            float4 v = p[i];
            s  += v.x + v.y + v.z + v.w;
            ss += v.x * v.x + v.y * v.y + v.z * v.z + v.w * v.w;
        }
    }
    __shared__ float sh[256], sh2[256];
    sh[threadIdx.x] = s; sh2[threadIdx.x] = ss;
    __syncthreads();
    for (int off = 128; off > 0; off >>= 1) {
        if (threadIdx.x < off) {
            sh[threadIdx.x]  += sh[threadIdx.x + off];
            sh2[threadIdx.x] += sh2[threadIdx.x + off];
        }
        __syncthreads();
    }
    if (threadIdx.x == 0) { g_sum1[c] = sh[0]; g_sq1[c] = sh2[0]; }
}

// ---------------------------------------------------------------------------
// Kernel 2: prep. Fold BN1 affine + theta_in interpolation into per-channel
// (A0,A1,O0,O1,d); precompute theta_out taps; transpose W. One block, 256 thr.
// ---------------------------------------------------------------------------
__global__ void k_prep(const float* __restrict__ conv_w,
                       const float* __restrict__ bn1_g,
                       const float* __restrict__ bn1_b,
                       const float* __restrict__ th_in,
                       const float* __restrict__ th_out) {
    int i = threadIdx.x;   // channel index (both c and o roles, CC==256)

    float mean = g_sum1[i] * (1.0f / NTV);
    float var  = g_sq1[i] * (1.0f / NTV) - mean * mean;
    float sc   = bn1_g[i] * rsqrtf(var + 1e-5f);
    float of   = bn1_b[i] - mean * sc;

    float th = th_in[i];
    float fd = floorf(th);
    float w1 = th - fd, w0 = 1.0f - w1;
    g_A0[i] = w0 * sc;  g_A1[i] = w1 * sc;
    g_O0[i] = w0 * of;  g_O1[i] = w1 * of;
    g_D[i]  = (int)fd;

    float tho = th_out[i];
    float fdo = floorf(tho);
    g_w1o[i] = tho - fdo;
    g_w0o[i] = 1.0f - (tho - fdo);
    g_Do[i]  = (int)fdo;

    // transpose weights: thread i owns output-row o=i (contiguous read)
    for (int k = 0; k < CC; k++)
        g_Wt[k * CC + i] = conv_w[i * CC + k];
}

// ---------------------------------------------------------------------------
// Kernel 3: fused (BN1+shift_in) -> GEMM -> +bias -> ReLU -> g_r
// Classic 128x128x32 tile, 256 threads, 8x8 per thread, float4 smem paths.
// A-tile (h) is constructed on the fly from raw x with folded coefficients.
// ---------------------------------------------------------------------------
#define BM 128
#define BK 32

__global__ __launch_bounds__(256, 2)
void k_gemm(const float* __restrict__ x, const float* __restrict__ conv_b) {
    __shared__ float hs[BK][BM + 4];
    __shared__ float ws[BK][BM + 4];
    __shared__ float cA0[CC], cA1[CC], cO0[CC], cO1[CC];
    __shared__ int   cD[CC];

    int tid = threadIdx.x;
    cA0[tid] = g_A0[tid]; cA1[tid] = g_A1[tid];
    cO0[tid] = g_O0[tid]; cO1[tid] = g_O1[tid];
    cD[tid]  = g_D[tid];

    int m0 = blockIdx.x * BM;
    int o0 = blockIdx.y * 128;

    // Each thread feeds hs[k][mLane] for one fixed m-lane, 16 k's per chunk.
    int mLane = tid & 127;
    int kBase = tid >> 7;                 // 0 or 1
    int mG = m0 + mLane;
    int n  = mG / TV;
    int q  = mG - n * TV;
    int t  = q / VV;
    int v  = q - t * VV;
    const float* xb = x + (size_t)n * XSTRIDE_N + t * VV + v;

    float acc[8][8];
#pragma unroll
    for (int i = 0; i < 8; i++)
#pragma unroll
        for (int j = 0; j < 8; j++) acc[i][j] = 0.f;

    int tx = tid & 15, ty = tid >> 4;
    __syncthreads();   // cA0..cD visible

    for (int kc = 0; kc < CC; kc += BK) {
        // ---- load W tile (32 k x 128 o), float4 ----
#pragma unroll
        for (int i = 0; i < 4; i++) {
            int f  = tid + 256 * i;
            int k  = f >> 5;
            int c4 = f & 31;
            float4 w = *(const float4*)(g_Wt + (kc + k) * CC + o0 + c4 * 4);
            *(float4*)(&ws[k][c4 * 4]) = w;
        }
        // ---- build h tile (32 k x 128 m): BN1 + shift folded ----
#pragma unroll
        for (int i = 0; i < 16; i++) {
            int k = kBase + 2 * i;
            int c = kc + k;
            int d = cD[c];
            const float* xc = xb + c * TV;
            float h = 0.f;
            int t0 = t + d;
            if (t0 >= 0 && t0 < TT)           h  = cA0[c] * xc[d * VV]        + cO0[c];
            if (t0 + 1 >= 0 && t0 + 1 < TT)   h += cA1[c] * xc[(d + 1) * VV]  + cO1[c];
            hs[k][mLane] = h;
        }
        __syncthreads();
        // ---- 8x8 register tile FMA ----
#pragma unroll
        for (int kk = 0; kk < BK; kk++) {
            float a[8], b[8];
            *(float4*)(a)     = *(const float4*)(&hs[kk][tx * 4]);
            *(float4*)(a + 4) = *(const float4*)(&hs[kk][tx * 4 + 64]);
            *(float4*)(b)     = *(const float4*)(&ws[kk][ty * 4]);
            *(float4*)(b + 4) = *(const float4*)(&ws[kk][ty * 4 + 64]);
#pragma unroll
            for (int i = 0; i < 8; i++)
#pragma unroll
                for (int j = 0; j < 8; j++)
                    acc[i][j] += b[i] * a[j];
        }
        __syncthreads();
    }

    // ---- epilogue: +bias, ReLU, store to g_r in (n,o,t,v) layout ----
#pragma unroll
    for (int ii = 0; ii < 2; ii++)
#pragma unroll
        for (int i2 = 0; i2 < 4; i2++) {
            int o = o0 + ty * 4 + i2 + 64 * ii;
            float bo = conv_b[o];
#pragma unroll
            for (int jj = 0; jj < 2; jj++) {
                int m  = m0 + tx * 4 + 64 * jj;
                int n_ = m / TV;
                int q_ = m - n_ * TV;   // m%4==0 and 1600%4==0 -> no n-crossing inside the float4
                float4 r;
                r.x = fmaxf(acc[ii * 4 + i2][jj * 4 + 0] + bo, 0.f);
                r.y = fmaxf(acc[ii * 4 + i2][jj * 4 + 1] + bo, 0.f);
                r.z = fmaxf(acc[ii * 4 + i2][jj * 4 + 2] + bo, 0.f);
                r.w = fmaxf(acc[ii * 4 + i2][jj * 4 + 3] + bo, 0.f);
                *(float4*)(g_r + (size_t)n_ * (CC * TV) + (size_t)o * TV + q_) = r;
            }
        }
}

// ---------------------------------------------------------------------------
// Kernel 4: output temporal shift + per-(n,o) partial BN2 stats.
// Grid (NN, CC); writes shifted y to d_out and deterministic partials.
// ---------------------------------------------------------------------------
__global__ void k_shift_stats(float* __restrict__ out) {
    int n = blockIdx.x, o = blockIdx.y;
    const float* rb = g_r + (size_t)(n * CC + o) * TV;
    float* ob = out + (size_t)(n * CC + o) * TV;
    int d = g_Do[o];
    float w0 = g_w0o[o], w1 = g_w1o[o];

    float s = 0.f, ss = 0.f;
    for (int q = threadIdx.x; q < TV; q += blockDim.x) {
        int t = q / VV;
        int v = q - t * VV;
        int t0 = t + d;
        float y = 0.f;
        if (t0 >= 0 && t0 < TT)         y  = w0 * rb[t0 * VV + v];
        if (t0 + 1 >= 0 && t0 + 1 < TT) y += w1 * rb[(t0 + 1) * VV + v];
        ob[q] = y;
        s += y; ss += y * y;
    }
    __shared__ float sh[256], sh2[256];
    sh[threadIdx.x] = s; sh2[threadIdx.x] = ss;
    __syncthreads();
    for (int off = 128; off > 0; off >>= 1) {
        if (threadIdx.x < off) {
            sh[threadIdx.x]  += sh[threadIdx.x + off];
            sh2[threadIdx.x] += sh2[threadIdx.x + off];
        }
        __syncthreads();
    }
    if (threadIdx.x == 0) {
        g_p2s[n * CC + o] = sh[0];
        g_p2q[n * CC + o] = sh2[0];
    }
}

// ---------------------------------------------------------------------------
// Kernel 5: finalize BN2 scale/offset. Deterministic 64-way reduction.
// ---------------------------------------------------------------------------
__global__ void k_fin(const float* __restrict__ bn2_g, const float* __restrict__ bn2_b) {
    int o = threadIdx.x;
    float s = 0.f, ss = 0.f;
    for (int n = 0; n < NN; n++) { s += g_p2s[n * CC + o]; ss += g_p2q[n * CC + o]; }
    float mean = s * (1.0f / NTV);
    float var  = ss * (1.0f / NTV) - mean * mean;
    float sc   = bn2_g[o] * rsqrtf(var + 1e-5f);
    g_sc2[o] = sc;
    g_of2[o] = bn2_b[o] - mean * sc;
}

// ---------------------------------------------------------------------------
// Kernel 6: apply BN2 affine in place on d_out (float4).
// ---------------------------------------------------------------------------
__global__ void k_norm(float* __restrict__ out) {
    int i4 = blockIdx.x * blockDim.x + threadIdx.x;          // float4 index
    if (i4 >= (NN * CC * TV) / 4) return;
    int e = i4 << 2;
    int o = (e / TV) & (CC - 1);                              // (e/1600) % 256
    float sc = g_sc2[o], of = g_of2[o];
    float4 v = ((float4*)out)[i4];
    v.x = v.x * sc + of; v.y = v.y * sc + of;
    v.z = v.z * sc + of; v.w = v.w * sc + of;
    ((float4*)out)[i4] = v;
}

// ---------------------------------------------------------------------------
// kernel_launch: inputs per metadata order:
// x, conv_w, conv_b, bn1_g, bn1_b, bn2_g, bn2_b, theta_in, theta_out
// ---------------------------------------------------------------------------
extern "C" void kernel_launch(void* const* d_in, const int* in_sizes, int n_in,
                              void* d_out, int out_size) {
    const float* x      = (const float*)d_in[0];
    const float* conv_w = (const float*)d_in[1];
    const float* conv_b = (const float*)d_in[2];
    const float* bn1_g  = (const float*)d_in[3];
    const float* bn1_b  = (const float*)d_in[4];
    const float* bn2_g  = (const float*)d_in[5];
    const float* bn2_b  = (const float*)d_in[6];
    const float* th_in  = (const float*)d_in[7];
    const float* th_out = (const float*)d_in[8];
    float* out = (float*)d_out;

    k_stats1<<<CC, 256>>>(x);
    k_prep<<<1, 256>>>(conv_w, bn1_g, bn1_b, th_in, th_out);
    k_gemm<<<dim3(MTOT / BM, 2), 256>>>(x, conv_b);
    k_shift_stats<<<dim3(NN, CC), 256>>>(out);
    k_fin<<<1, 256>>>(bn2_g, bn2_b);
    k_norm<<<(NN * CC * TV / 4 + 255) / 256, 256>>>(out);
}

// round 10
// speedup vs baseline: 1.0019x; 1.0019x over previous
#include <cuda_runtime.h>
#include <math.h>

// Problem constants
#define NN 64
#define CC 256
#define TT 64
#define VV 25
#define TV 1600          // T*V
#define NTV 102400       // N*T*V (per-channel element count)
#define MTOT 102400      // N*TV  (GEMM M dimension)
#define XSTRIDE_N (CC*TV)

// Scratch (device globals: allocations are forbidden)
__device__ float g_r[(size_t)NN*CC*TV];   // relu(conv) output, layout (n,o,t,v)
__device__ float g_Wt[CC*CC];             // transposed weights: Wt[c*CC + o] = W[o,c]
__device__ float g_sum1[CC], g_sq1[CC];   // BN1 raw stats
// folded BN1 + input-shift coefficients (per input channel c)
__device__ float g_A0[CC], g_A1[CC], g_O0[CC], g_O1[CC];
__device__ int   g_D[CC];
// output-shift coefficients (per output channel o)
__device__ float g_w0o[CC], g_w1o[CC];
__device__ int   g_Do[CC];
// BN2 partial stats (per n, per o) -> deterministic reduction in finalize
__device__ float g_p2s[NN*CC], g_p2q[NN*CC];
__device__ float g_sc2[CC], g_of2[CC];

// ---------------------------------------------------------------------------
// Kernel 1: BN1 stats. One block per channel c; reduce sum & sumsq over n,t,v.
// ---------------------------------------------------------------------------
__global__ void k_stats1(const float* __restrict__ x) {
    int c = blockIdx.x;
    float s = 0.f, ss = 0.f;
    for (int n = 0; n < NN; n++) {
        const float4* p = (const float4*)(x + (size_t)(n * CC + c) * TV);
        for (int i = threadIdx.x; i < TV / 4; i += blockDim.x) {
            float4 v = p[i];
            s  += v.x + v.y + v.z + v.w;
            ss += v.x * v.x + v.y * v.y + v.z * v.z + v.w * v.w;
        }
    }
    __shared__ float sh[256], sh2[256];
    sh[threadIdx.x] = s; sh2[threadIdx.x] = ss;
    __syncthreads();
    for (int off = 128; off > 0; off >>= 1) {
        if (threadIdx.x < off) {
            sh[threadIdx.x]  += sh[threadIdx.x + off];
            sh2[threadIdx.x] += sh2[threadIdx.x + off];
        }
        __syncthreads();
    }
    if (threadIdx.x == 0) { g_sum1[c] = sh[0]; g_sq1[c] = sh2[0]; }
}

// ---------------------------------------------------------------------------
// Kernel 2: prep. Fold BN1 affine + theta_in interpolation into per-channel
// (A0,A1,O0,O1,d); precompute theta_out taps; transpose W. One block, 256 thr.
// ---------------------------------------------------------------------------
__global__ void k_prep(const float* __restrict__ conv_w,
                       const float* __restrict__ bn1_g,
                       const float* __restrict__ bn1_b,
                       const float* __restrict__ th_in,
                       const float* __restrict__ th_out) {
    int i = threadIdx.x;   // channel index (both c and o roles, CC==256)

    float mean = g_sum1[i] * (1.0f / NTV);
    float var  = g_sq1[i] * (1.0f / NTV) - mean * mean;
    float sc   = bn1_g[i] * rsqrtf(var + 1e-5f);
    float of   = bn1_b[i] - mean * sc;

    float th = th_in[i];
    float fd = floorf(th);
    float w1 = th - fd, w0 = 1.0f - w1;
    g_A0[i] = w0 * sc;  g_A1[i] = w1 * sc;
    g_O0[i] = w0 * of;  g_O1[i] = w1 * of;
    g_D[i]  = (int)fd;

    float tho = th_out[i];
    float fdo = floorf(tho);
    g_w1o[i] = tho - fdo;
    g_w0o[i] = 1.0f - (tho - fdo);
    g_Do[i]  = (int)fdo;

    // transpose weights: thread i owns output-row o=i (contiguous read)
    for (int k = 0; k < CC; k++)
        g_Wt[k * CC + i] = conv_w[i * CC + k];
}

// ---------------------------------------------------------------------------
// Kernel 3: fused (BN1+shift_in) -> GEMM -> +bias -> ReLU -> g_r
// Classic 128x128x32 tile, 256 threads, 8x8 per thread, float4 smem paths.
// A-tile (h) is constructed on the fly from raw x with folded coefficients.
// ---------------------------------------------------------------------------
#define BM 128
#define BK 32

__global__ __launch_bounds__(256, 2)
void k_gemm(const float* __restrict__ x, const float* __restrict__ conv_b) {
    __shared__ float hs[BK][BM + 4];
    __shared__ float ws[BK][BM + 4];
    __shared__ float cA0[CC], cA1[CC], cO0[CC], cO1[CC];
    __shared__ int   cD[CC];

    int tid = threadIdx.x;
    cA0[tid] = g_A0[tid]; cA1[tid] = g_A1[tid];
    cO0[tid] = g_O0[tid]; cO1[tid] = g_O1[tid];
    cD[tid]  = g_D[tid];

    int m0 = blockIdx.x * BM;
    int o0 = blockIdx.y * 128;

    // Each thread feeds hs[k][mLane] for one fixed m-lane, 16 k's per chunk.
    int mLane = tid & 127;
    int kBase = tid >> 7;                 // 0 or 1
    int mG = m0 + mLane;
    int n  = mG / TV;
    int q  = mG - n * TV;
    int t  = q / VV;
    int v  = q - t * VV;
    const float* xb = x + (size_t)n * XSTRIDE_N + t * VV + v;

    float acc[8][8];
#pragma unroll
    for (int i = 0; i < 8; i++)
#pragma unroll
        for (int j = 0; j < 8; j++) acc[i][j] = 0.f;

    int tx = tid & 15, ty = tid >> 4;
    __syncthreads();   // cA0..cD visible

    for (int kc = 0; kc < CC; kc += BK) {
        // ---- load W tile (32 k x 128 o), float4 ----
#pragma unroll
        for (int i = 0; i < 4; i++) {
            int f  = tid + 256 * i;
            int k  = f >> 5;
            int c4 = f & 31;
            float4 w = *(const float4*)(g_Wt + (kc + k) * CC + o0 + c4 * 4);
            *(float4*)(&ws[k][c4 * 4]) = w;
        }
        // ---- build h tile (32 k x 128 m): BN1 + shift folded ----
#pragma unroll
        for (int i = 0; i < 16; i++) {
            int k = kBase + 2 * i;
            int c = kc + k;
            int d = cD[c];
            const float* xc = xb + c * TV;
            float h = 0.f;
            int t0 = t + d;
            if (t0 >= 0 && t0 < TT)           h  = cA0[c] * xc[d * VV]        + cO0[c];
            if (t0 + 1 >= 0 && t0 + 1 < TT)   h += cA1[c] * xc[(d + 1) * VV]  + cO1[c];
            hs[k][mLane] = h;
        }
        __syncthreads();
        // ---- 8x8 register tile FMA ----
#pragma unroll
        for (int kk = 0; kk < BK; kk++) {
            float a[8], b[8];
            *(float4*)(a)     = *(const float4*)(&hs[kk][tx * 4]);
            *(float4*)(a + 4) = *(const float4*)(&hs[kk][tx * 4 + 64]);
            *(float4*)(b)     = *(const float4*)(&ws[kk][ty * 4]);
            *(float4*)(b + 4) = *(const float4*)(&ws[kk][ty * 4 + 64]);
#pragma unroll
            for (int i = 0; i < 8; i++)
#pragma unroll
                for (int j = 0; j < 8; j++)
                    acc[i][j] += b[i] * a[j];
        }
        __syncthreads();
    }

    // ---- epilogue: +bias, ReLU, store to g_r in (n,o,t,v) layout ----
#pragma unroll
    for (int ii = 0; ii < 2; ii++)
#pragma unroll
        for (int i2 = 0; i2 < 4; i2++) {
            int o = o0 + ty * 4 + i2 + 64 * ii;
            float bo = conv_b[o];
#pragma unroll
            for (int jj = 0; jj < 2; jj++) {
                int m  = m0 + tx * 4 + 64 * jj;
                int n_ = m / TV;
                int q_ = m - n_ * TV;   // m%4==0 and 1600%4==0 -> no n-crossing inside the float4
                float4 r;
                r.x = fmaxf(acc[ii * 4 + i2][jj * 4 + 0] + bo, 0.f);
                r.y = fmaxf(acc[ii * 4 + i2][jj * 4 + 1] + bo, 0.f);
                r.z = fmaxf(acc[ii * 4 + i2][jj * 4 + 2] + bo, 0.f);
                r.w = fmaxf(acc[ii * 4 + i2][jj * 4 + 3] + bo, 0.f);
                *(float4*)(g_r + (size_t)n_ * (CC * TV) + (size_t)o * TV + q_) = r;
            }
        }
}

// ---------------------------------------------------------------------------
// Kernel 4: output temporal shift + per-(n,o) partial BN2 stats.
// Grid (NN, CC); writes shifted y to d_out and deterministic partials.
// ---------------------------------------------------------------------------
__global__ void k_shift_stats(float* __restrict__ out) {
    int n = blockIdx.x, o = blockIdx.y;
    const float* rb = g_r + (size_t)(n * CC + o) * TV;
    float* ob = out + (size_t)(n * CC + o) * TV;
    int d = g_Do[o];
    float w0 = g_w0o[o], w1 = g_w1o[o];

    float s = 0.f, ss = 0.f;
    for (int q = threadIdx.x; q < TV; q += blockDim.x) {
        int t = q / VV;
        int v = q - t * VV;
        int t0 = t + d;
        float y = 0.f;
        if (t0 >= 0 && t0 < TT)         y  = w0 * rb[t0 * VV + v];
        if (t0 + 1 >= 0 && t0 + 1 < TT) y += w1 * rb[(t0 + 1) * VV + v];
        ob[q] = y;
        s += y; ss += y * y;
    }
    __shared__ float sh[256], sh2[256];
    sh[threadIdx.x] = s; sh2[threadIdx.x] = ss;
    __syncthreads();
    for (int off = 128; off > 0; off >>= 1) {
        if (threadIdx.x < off) {
            sh[threadIdx.x]  += sh[threadIdx.x + off];
            sh2[threadIdx.x] += sh2[threadIdx.x + off];
        }
        __syncthreads();
    }
    if (threadIdx.x == 0) {
        g_p2s[n * CC + o] = sh[0];
        g_p2q[n * CC + o] = sh2[0];
    }
}

// ---------------------------------------------------------------------------
// Kernel 5: finalize BN2 scale/offset. Deterministic 64-way reduction.
// ---------------------------------------------------------------------------
__global__ void k_fin(const float* __restrict__ bn2_g, const float* __restrict__ bn2_b) {
    int o = threadIdx.x;
    float s = 0.f, ss = 0.f;
    for (int n = 0; n < NN; n++) { s += g_p2s[n * CC + o]; ss += g_p2q[n * CC + o]; }
    float mean = s * (1.0f / NTV);
    float var  = ss * (1.0f / NTV) - mean * mean;
    float sc   = bn2_g[o] * rsqrtf(var + 1e-5f);
    g_sc2[o] = sc;
    g_of2[o] = bn2_b[o] - mean * sc;
}

// ---------------------------------------------------------------------------
// Kernel 6: apply BN2 affine in place on d_out (float4).
// ---------------------------------------------------------------------------
__global__ void k_norm(float* __restrict__ out) {
    int i4 = blockIdx.x * blockDim.x + threadIdx.x;          // float4 index
    if (i4 >= (NN * CC * TV) / 4) return;
    int e = i4 << 2;
    int o = (e / TV) & (CC - 1);                              // (e/1600) % 256
    float sc = g_sc2[o], of = g_of2[o];
    float4 v = ((float4*)out)[i4];
    v.x = v.x * sc + of; v.y = v.y * sc + of;
    v.z = v.z * sc + of; v.w = v.w * sc + of;
    ((float4*)out)[i4] = v;
}

// ---------------------------------------------------------------------------
// kernel_launch: inputs per metadata order:
// x, conv_w, conv_b, bn1_g, bn1_b, bn2_g, bn2_b, theta_in, theta_out
// ---------------------------------------------------------------------------
extern "C" void kernel_launch(void* const* d_in, const int* in_sizes, int n_in,
                              void* d_out, int out_size) {
    const float* x      = (const float*)d_in[0];
    const float* conv_w = (const float*)d_in[1];
    const float* conv_b = (const float*)d_in[2];
    const float* bn1_g  = (const float*)d_in[3];
    const float* bn1_b  = (const float*)d_in[4];
    const float* bn2_g  = (const float*)d_in[5];
    const float* bn2_b  = (const float*)d_in[6];
    const float* th_in  = (const float*)d_in[7];
    const float* th_out = (const float*)d_in[8];
    float* out = (float*)d_out;

    k_stats1<<<CC, 256>>>(x);
    k_prep<<<1, 256>>>(conv_w, bn1_g, bn1_b, th_in, th_out);
    k_gemm<<<dim3(MTOT / BM, 2), 256>>>(x, conv_b);
    k_shift_stats<<<dim3(NN, CC), 256>>>(out);
    k_fin<<<1, 256>>>(bn2_g, bn2_b);
    k_norm<<<(NN * CC * TV / 4 + 255) / 256, 256>>>(out);
}